// round 3
// baseline (speedup 1.0000x reference)
#include <cuda_runtime.h>
#include <cstdint>

#define D 4096
#define NV4 (D / 4)        // 1024 float4 per row
#define THREADS 256
#define EPS 1e-6f

__global__ __launch_bounds__(THREADS, 8) void mrmsnorm_kernel(
    const float4* __restrict__ x,
    const float4* __restrict__ scale,
    float4* __restrict__ out)
{
    __shared__ float4 sx[NV4];          // 16 KB row stage
    __shared__ float ws[8][3];

    const size_t row = blockIdx.x;
    const float4* __restrict__ xr = x + row * NV4;
    float4* __restrict__ orow = out + row * NV4;

    const int t = threadIdx.x;
    const int warp = t >> 5;
    const int lane = t & 31;

    // Stage the row into smem with cp.async (no destination registers,
    // 4 front-batched 16B LDGSTS per thread -> high MLP at 8 CTAs/SM).
    {
        uint32_t s0 = (uint32_t)__cvta_generic_to_shared(&sx[t]);
        uint32_t s1 = (uint32_t)__cvta_generic_to_shared(&sx[t + THREADS]);
        uint32_t s2 = (uint32_t)__cvta_generic_to_shared(&sx[t + 2 * THREADS]);
        uint32_t s3 = (uint32_t)__cvta_generic_to_shared(&sx[t + 3 * THREADS]);
        asm volatile("cp.async.cg.shared.global [%0], [%1], 16;\n"
                     "cp.async.cg.shared.global [%2], [%3], 16;\n"
                     "cp.async.cg.shared.global [%4], [%5], 16;\n"
                     "cp.async.cg.shared.global [%6], [%7], 16;\n"
                     :: "r"(s0), "l"(&xr[t]),
                        "r"(s1), "l"(&xr[t + THREADS]),
                        "r"(s2), "l"(&xr[t + 2 * THREADS]),
                        "r"(s3), "l"(&xr[t + 3 * THREADS]));
        asm volatile("cp.async.commit_group;");
        asm volatile("cp.async.wait_group 0;");
    }
    __syncthreads();

    // Pass 1: reduce sum-of-squares per slice (values not kept).
    float sa, sb, scd;
    {
        float4 a = sx[t];
        float4 b = sx[t + THREADS];
        float4 c = sx[t + 2 * THREADS];
        float4 d = sx[t + 3 * THREADS];
        sa = a.x * a.x + a.y * a.y + a.z * a.z + a.w * a.w;
        sb = b.x * b.x + b.y * b.y + b.z * b.z + b.w * b.w;
        float sc = c.x * c.x + c.y * c.y + c.z * c.z + c.w * c.w;
        float sd = d.x * d.x + d.y * d.y + d.z * d.z + d.w * d.w;
        scd = sc + sd;
    }

    #pragma unroll
    for (int o = 16; o > 0; o >>= 1) {
        sa  += __shfl_down_sync(0xffffffffu, sa, o);
        sb  += __shfl_down_sync(0xffffffffu, sb, o);
        scd += __shfl_down_sync(0xffffffffu, scd, o);
    }

    if (lane == 0) {
        ws[warp][0] = sa;
        ws[warp][1] = sb;
        ws[warp][2] = scd;
    }
    __syncthreads();

    // Segment sums (float4-index ranges: seg0 [0,64), seg1 [64,128),
    // seg2 [128,256), seg3 [256,512), seg4 [512,1024)).
    float seg0 = ws[0][0] + ws[1][0];
    float seg1 = ws[2][0] + ws[3][0];
    float seg2 = ws[4][0] + ws[5][0] + ws[6][0] + ws[7][0];
    float seg3 = ws[0][1] + ws[1][1] + ws[2][1] + ws[3][1]
               + ws[4][1] + ws[5][1] + ws[6][1] + ws[7][1];
    float seg4 = ws[0][2] + ws[1][2] + ws[2][2] + ws[3][2]
               + ws[4][2] + ws[5][2] + ws[6][2] + ws[7][2];

    float c0 = seg0;
    float c1 = c0 + seg1;
    float c2 = c1 + seg2;
    float c3 = c2 + seg3;
    float c4 = c3 + seg4;

    float r0 = rsqrtf(c0 * (1.0f / 256.0f)  + EPS);
    float r1 = rsqrtf(c1 * (1.0f / 512.0f)  + EPS);
    float r2 = rsqrtf(c2 * (1.0f / 1024.0f) + EPS);
    float r3 = rsqrtf(c3 * (1.0f / 2048.0f) + EPS);
    float r4 = rsqrtf(c4 * (1.0f / 4096.0f) + EPS);

    float ra = (t < 64) ? r0 : (t < 128) ? r1 : r2;   // warp-uniform
    float rb = r3;
    float rc = r4;

    // Pass 2: re-read smem, apply rrms * scale, streaming store.
    {
        float4 a = sx[t];
        float4 s = scale[t];
        float4 o;
        o.x = a.x * ra * s.x;  o.y = a.y * ra * s.y;
        o.z = a.z * ra * s.z;  o.w = a.w * ra * s.w;
        __stcs(&orow[t], o);
    }
    {
        float4 a = sx[t + THREADS];
        float4 s = scale[t + THREADS];
        float4 o;
        o.x = a.x * rb * s.x;  o.y = a.y * rb * s.y;
        o.z = a.z * rb * s.z;  o.w = a.w * rb * s.w;
        __stcs(&orow[t + THREADS], o);
    }
    {
        float4 a = sx[t + 2 * THREADS];
        float4 s = scale[t + 2 * THREADS];
        float4 o;
        o.x = a.x * rc * s.x;  o.y = a.y * rc * s.y;
        o.z = a.z * rc * s.z;  o.w = a.w * rc * s.w;
        __stcs(&orow[t + 2 * THREADS], o);
    }
    {
        float4 a = sx[t + 3 * THREADS];
        float4 s = scale[t + 3 * THREADS];
        float4 o;
        o.x = a.x * rc * s.x;  o.y = a.y * rc * s.y;
        o.z = a.z * rc * s.z;  o.w = a.w * rc * s.w;
        __stcs(&orow[t + 3 * THREADS], o);
    }
}

extern "C" void kernel_launch(void* const* d_in, const int* in_sizes, int n_in,
                              void* d_out, int out_size)
{
    const float4* x = (const float4*)d_in[0];
    const float4* scale = (const float4*)d_in[1];
    float4* out = (float4*)d_out;

    const int rows = out_size / D;   // 4 * 4096 = 16384
    mrmsnorm_kernel<<<rows, THREADS>>>(x, scale, out);
}